// round 1
// baseline (speedup 1.0000x reference)
#include <cuda_runtime.h>
#include <cuda_bf16.h>
#include <math.h>

// Problem constants
#define BB 16
#define LL 512
#define DD 768
#define HH 12
#define KDIM 64
#define FF 3072
#define NLAYER 12
#define NTOK (BB*LL)            // 8192

// ---------------- device scratch (static globals; no runtime allocation) ----
__device__ float g_h[NTOK*DD];
__device__ float g_x[NTOK*DD];
__device__ float g_q[NTOK*DD];
__device__ float g_k[NTOK*DD];
__device__ float g_v[NTOK*DD];
__device__ float g_ao[NTOK*DD];
__device__ float g_ff[NTOK*FF];
__device__ float g_scores[(long long)BB*HH*LL*LL]; // 192*512*512 = 50,331,648 floats
__device__ float g_csim[BB*LL*LL];                 // 16*512*512
__device__ int   g_pos[BB*LL];
__device__ float g_pooled[BB*DD];

// ---------------- reductions ----------------
__device__ __forceinline__ float warpSum(float v){
    #pragma unroll
    for (int o=16;o>0;o>>=1) v += __shfl_xor_sync(0xffffffffu, v, o);
    return v;
}
__device__ __forceinline__ float warpMax(float v){
    #pragma unroll
    for (int o=16;o>0;o>>=1) v = fmaxf(v, __shfl_xor_sync(0xffffffffu, v, o));
    return v;
}
__device__ float blockSum(float v){
    __shared__ float sh[32];
    int lane = threadIdx.x & 31, wid = threadIdx.x >> 5;
    v = warpSum(v);
    if (lane==0) sh[wid] = v;
    __syncthreads();
    int nw = (blockDim.x + 31) >> 5;
    float r = (threadIdx.x < nw) ? sh[threadIdx.x] : 0.f;
    if (wid==0) r = warpSum(r);
    if (threadIdx.x==0) sh[0] = r;
    __syncthreads();
    r = sh[0];
    __syncthreads();
    return r;
}
__device__ float blockMax(float v){
    __shared__ float sh[32];
    int lane = threadIdx.x & 31, wid = threadIdx.x >> 5;
    v = warpMax(v);
    if (lane==0) sh[wid] = v;
    __syncthreads();
    int nw = (blockDim.x + 31) >> 5;
    float r = (threadIdx.x < nw) ? sh[threadIdx.x] : -INFINITY;
    if (wid==0) r = warpMax(r);
    if (threadIdx.x==0) sh[0] = r;
    __syncthreads();
    r = sh[0];
    __syncthreads();
    return r;
}

// ---------------- batched SGEMM: C = act(alpha*A@B(^T) + bias) ---------------
// Tiles: 128x128x8, 256 threads, 8x8 per-thread micro-tile.
// Batch addressing: z -> (zo=z/mapdiv, zi=z%mapdiv);
//   A base += zo*sAo + zi*sAi ; B base += (bmap?bmap[zo]:zo)*sBo + zi*sBi ;
//   C base += zo*sCo + zi*sCi.
template<bool TB>
__global__ __launch_bounds__(256)
void sgemm_kernel(const float* __restrict__ A, const float* __restrict__ B,
                  const float* __restrict__ bias, float* __restrict__ C,
                  int M, int N, int K, int lda, int ldb, int ldc,
                  int mapdiv,
                  long long sAo, long long sAi,
                  long long sBo, long long sBi,
                  long long sCo, long long sCi,
                  const int* __restrict__ bmap,
                  float alpha, int act)
{
    __shared__ float As[8][128];
    __shared__ float Bs[8][128];

    int z = blockIdx.z;
    int zo = z / mapdiv, zi = z - zo*mapdiv;
    const float* Ab = A + (long long)zo*sAo + (long long)zi*sAi;
    long long bzo = bmap ? (long long)bmap[zo] : (long long)zo;
    const float* Bb = B + bzo*sBo + (long long)zi*sBi;
    float* Cb = C + (long long)zo*sCo + (long long)zi*sCi;

    int bm = blockIdx.y * 128;
    int bn = blockIdx.x * 128;
    int tid = threadIdx.x;
    int tx = tid & 15, ty = tid >> 4;

    float acc[8][8];
    #pragma unroll
    for (int i=0;i<8;i++)
        #pragma unroll
        for (int j=0;j<8;j++) acc[i][j]=0.f;

    int arow = tid >> 1;
    int acol0 = (tid & 1) * 4;

    for (int k0 = 0; k0 < K; k0 += 8) {
        // A tile (stored transposed): As[k][m]
        #pragma unroll
        for (int i=0;i<4;i++){
            int kk = acol0 + i;
            int gm = bm + arow;
            float val = 0.f;
            if (gm < M && (k0+kk) < K) val = Ab[(long long)gm*lda + (k0+kk)];
            As[kk][arow] = val;
        }
        if (!TB) {
            int brow = tid >> 5;            // 0..7 (k)
            int bcol0 = (tid & 31) * 4;     // n
            #pragma unroll
            for (int i=0;i<4;i++){
                int nn = bcol0 + i;
                float val = 0.f;
                if ((k0+brow) < K && (bn+nn) < N) val = Bb[(long long)(k0+brow)*ldb + (bn+nn)];
                Bs[brow][nn] = val;
            }
        } else {
            int nrow = tid >> 1;            // n
            int kcol0 = (tid & 1) * 4;      // k
            #pragma unroll
            for (int i=0;i<4;i++){
                int kk = kcol0 + i;
                float val = 0.f;
                if ((bn+nrow) < N && (k0+kk) < K) val = Bb[(long long)(bn+nrow)*ldb + (k0+kk)];
                Bs[kk][nrow] = val;
            }
        }
        __syncthreads();
        #pragma unroll
        for (int kk=0; kk<8; kk++){
            float ar[8], br[8];
            #pragma unroll
            for (int i=0;i<8;i++) ar[i] = As[kk][ty*8+i];
            #pragma unroll
            for (int j=0;j<8;j++) br[j] = Bs[kk][tx*8+j];
            #pragma unroll
            for (int i=0;i<8;i++)
                #pragma unroll
                for (int j=0;j<8;j++)
                    acc[i][j] = fmaf(ar[i], br[j], acc[i][j]);
        }
        __syncthreads();
    }

    #pragma unroll
    for (int i=0;i<8;i++){
        int gm = bm + ty*8 + i;
        if (gm >= M) continue;
        #pragma unroll
        for (int j=0;j<8;j++){
            int gn = bn + tx*8 + j;
            if (gn >= N) continue;
            float val = acc[i][j]*alpha;
            if (bias) val += bias[gn];
            if (act==1) val = 0.5f*val*(1.0f + erff(val*0.70710678118654752f));
            Cb[(long long)gm*ldc + gn] = val;
        }
    }
}

// ---------------- embedding + LN ----------------
__global__ void embed_kernel(const int* __restrict__ ids,
                             const float* __restrict__ we,
                             const float* __restrict__ pe,
                             const float* __restrict__ te,
                             const float* __restrict__ w,
                             const float* __restrict__ b,
                             float* __restrict__ h)
{
    int t = blockIdx.x;           // token index 0..8191
    int l = t % LL;
    int id = ids[t];
    float x[3];
    #pragma unroll
    for (int i=0;i<3;i++){
        int d = threadIdx.x + i*256;
        x[i] = we[(long long)id*DD + d] + pe[l*DD + d] + te[d];
    }
    float s = x[0]+x[1]+x[2];
    s = blockSum(s);
    float mu = s * (1.f/DD);
    float vs = 0.f;
    #pragma unroll
    for (int i=0;i<3;i++){ float dfr = x[i]-mu; vs += dfr*dfr; }
    vs = blockSum(vs);
    float inv = rsqrtf(vs*(1.f/DD) + 1e-12f);
    #pragma unroll
    for (int i=0;i<3;i++){
        int d = threadIdx.x + i*256;
        h[(long long)t*DD + d] = (x[i]-mu)*inv*w[d] + b[d];
    }
}

// ---------------- residual add + LN (in place on h) ----------------
__global__ void add_ln_kernel(float* __restrict__ h, const float* __restrict__ r,
                              const float* __restrict__ w, const float* __restrict__ b)
{
    int t = blockIdx.x;
    float x[3];
    #pragma unroll
    for (int i=0;i<3;i++){
        int d = threadIdx.x + i*256;
        long long idx = (long long)t*DD + d;
        x[i] = h[idx] + r[idx];
    }
    float s = x[0]+x[1]+x[2];
    s = blockSum(s);
    float mu = s * (1.f/DD);
    float vs = 0.f;
    #pragma unroll
    for (int i=0;i<3;i++){ float dfr = x[i]-mu; vs += dfr*dfr; }
    vs = blockSum(vs);
    float inv = rsqrtf(vs*(1.f/DD) + 1e-12f);
    #pragma unroll
    for (int i=0;i<3;i++){
        int d = threadIdx.x + i*256;
        h[(long long)t*DD + d] = (x[i]-mu)*inv*w[d] + b[d];
    }
}

// ---------------- masked softmax over last dim (rows of length 512) ---------
// masked_softmax: mv=v*m; mx=max(mv); ex=exp(mv-mx)*m; s=sum(ex); s+= (s==0); v=ex/s
__global__ void softmax_kernel(float* __restrict__ sc, const float* __restrict__ amask,
                               const int* __restrict__ mix, int HL)
{
    int r = blockIdx.x;                 // 0 .. B*H*L-1
    int b = r / HL;
    float* row = sc + (long long)r * LL;
    int mb = mix ? mix[b] : b;
    const float* m = amask + (long long)mb * LL;

    float vals[4], ms[4];
    float mx = -INFINITY;
    #pragma unroll
    for (int i=0;i<4;i++){
        int j = threadIdx.x + i*128;
        ms[i] = m[j];
        vals[i] = row[j]*ms[i];
        mx = fmaxf(mx, vals[i]);
    }
    mx = blockMax(mx);
    float s = 0.f;
    #pragma unroll
    for (int i=0;i<4;i++){
        vals[i] = expf(vals[i]-mx)*ms[i];
        s += vals[i];
    }
    s = blockSum(s);
    if (s == 0.f) s = 1.f;
    float inv = 1.f/s;
    #pragma unroll
    for (int i=0;i<4;i++){
        int j = threadIdx.x + i*128;
        row[j] = vals[i]*inv;
    }
}

// ---------------- cross_sim = max over heads of softmaxed cross scores ------
__global__ void crossmax_kernel(const float* __restrict__ sc, float* __restrict__ cs)
{
    int r = blockIdx.x;      // b*L + l
    int b = r / LL;
    int l = r % LL;
    #pragma unroll
    for (int i=0;i<4;i++){
        int j = threadIdx.x + i*128;
        float mx = -INFINITY;
        #pragma unroll
        for (int hh=0; hh<HH; hh++){
            mx = fmaxf(mx, sc[(((long long)(b*HH+hh))*LL + l)*LL + j]);
        }
        cs[(long long)r*LL + j] = mx;
    }
}

// ---------------- masked argmax with rank tie-breaking (later index wins) ---
__global__ void argmax_kernel(const float* __restrict__ cs, int* __restrict__ pos)
{
    int idx = blockIdx.x*blockDim.x + threadIdx.x;   // b*L + l
    if (idx >= BB*LL) return;
    int l = idx % LL;
    int lo, hi;
    if (l == 0)        { lo = 0;     hi = 0;     }
    else if (l == LL-1){ lo = LL-1;  hi = LL-1;  }
    else               { lo = 1;     hi = LL-2;  }
    const float* row = cs + (long long)idx*LL;
    float best = -INFINITY; int bi = lo;
    for (int j=lo; j<=hi; j++){
        float v = row[j];
        if (v >= best){ best = v; bi = j; }   // ties -> larger index (rank semantics)
    }
    pos[idx] = bi;
}

// ---------------- mixup blend: out = a*h + (1-a)*h[mix[b], pos[b,l]] --------
__global__ void blend_kernel(const float* __restrict__ h, const int* __restrict__ pos,
                             const int* __restrict__ mix, const float* __restrict__ alpha_p,
                             float* __restrict__ out)
{
    long long i = (long long)blockIdx.x*blockDim.x + threadIdx.x;
    if (i >= (long long)NTOK*DD) return;
    int d = (int)(i % DD);
    long long t = i / DD;
    int b = (int)(t / LL);
    float a = *alpha_p;
    int p = pos[t];
    float h2 = h[((long long)(mix[b]*LL + p))*DD + d];
    out[i] = a*h[i] + (1.f-a)*h2;
}

// ---------------- pooling (mean over L) ----------------
__global__ void pool_kernel(const float* __restrict__ h, float* __restrict__ pooled)
{
    int i = blockIdx.x*blockDim.x + threadIdx.x;  // b*768 + d
    if (i >= BB*DD) return;
    int b = i / DD, d = i % DD;
    float s = 0.f;
    for (int l=0; l<LL; l++) s += h[((long long)b*LL + l)*DD + d];
    pooled[i] = s * (1.f/LL);
}

// ---------------- classifier head ----------------
__global__ void head_kernel(const float* __restrict__ pooled,
                            const float* __restrict__ c1w, const float* __restrict__ c1b,
                            const float* __restrict__ c2w, const float* __restrict__ c2b,
                            float* __restrict__ out)
{
    __shared__ float hid[128];
    int b = blockIdx.x;
    int j = threadIdx.x;
    float s = c1b[j];
    for (int d=0; d<DD; d++) s += pooled[b*DD + d] * c1w[d*128 + j];
    hid[j] = tanhf(s);
    __syncthreads();
    if (j < 4){
        float o = c2b[j];
        for (int kk=0; kk<128; kk++) o += hid[kk]*c2w[kk*4 + j];
        out[b*4 + j] = o;
    }
}

// ---------------- host-side gemm wrapper ----------------
static void launch_gemm(const float* A, const float* B, const float* bias, float* C,
                        int M, int N, int K, int lda, int ldb, int ldc,
                        int batches, int mapdiv,
                        long long sAo, long long sAi,
                        long long sBo, long long sBi,
                        long long sCo, long long sCi,
                        const int* bmap, float alpha, int act, bool transB)
{
    dim3 grid((N+127)/128, (M+127)/128, batches);
    if (transB)
        sgemm_kernel<true><<<grid, 256>>>(A,B,bias,C,M,N,K,lda,ldb,ldc,mapdiv,
                                          sAo,sAi,sBo,sBi,sCo,sCi,bmap,alpha,act);
    else
        sgemm_kernel<false><<<grid, 256>>>(A,B,bias,C,M,N,K,lda,ldb,ldc,mapdiv,
                                           sAo,sAi,sBo,sBi,sCo,sCi,bmap,alpha,act);
}

extern "C" void kernel_launch(void* const* d_in, const int* in_sizes, int n_in,
                              void* d_out, int out_size)
{
    const int*   ids    = (const int*)  d_in[0];
    const float* amask  = (const float*)d_in[1];
    const int*   mix    = (const int*)  d_in[2];
    // d_in[3..5]: is_cls / is_sep / is_normal (structural: pos==0 / pos==L-1 / interior)
    const float* alpha  = (const float*)d_in[6];
    const float* we     = (const float*)d_in[7];
    const float* pe     = (const float*)d_in[8];
    const float* te     = (const float*)d_in[9];
    const float* elnw   = (const float*)d_in[10];
    const float* elnb   = (const float*)d_in[11];
    const float* Wq     = (const float*)d_in[12];
    const float* bq     = (const float*)d_in[13];
    const float* Wk     = (const float*)d_in[14];
    const float* bk     = (const float*)d_in[15];
    const float* Wv     = (const float*)d_in[16];
    const float* bv     = (const float*)d_in[17];
    const float* Wo     = (const float*)d_in[18];
    const float* bo     = (const float*)d_in[19];
    const float* ln1w   = (const float*)d_in[20];
    const float* ln1b   = (const float*)d_in[21];
    const float* Wf1    = (const float*)d_in[22];
    const float* bf1    = (const float*)d_in[23];
    const float* Wf2    = (const float*)d_in[24];
    const float* bf2    = (const float*)d_in[25];
    const float* ln2w   = (const float*)d_in[26];
    const float* ln2b   = (const float*)d_in[27];
    const float* c1w    = (const float*)d_in[28];
    const float* c1b    = (const float*)d_in[29];
    const float* c2w    = (const float*)d_in[30];
    const float* c2b    = (const float*)d_in[31];

    float *h, *x, *q, *k, *v, *ao, *ff, *sc, *cs, *pooled;
    int *pos;
    cudaGetSymbolAddress((void**)&h,  g_h);
    cudaGetSymbolAddress((void**)&x,  g_x);
    cudaGetSymbolAddress((void**)&q,  g_q);
    cudaGetSymbolAddress((void**)&k,  g_k);
    cudaGetSymbolAddress((void**)&v,  g_v);
    cudaGetSymbolAddress((void**)&ao, g_ao);
    cudaGetSymbolAddress((void**)&ff, g_ff);
    cudaGetSymbolAddress((void**)&sc, g_scores);
    cudaGetSymbolAddress((void**)&cs, g_csim);
    cudaGetSymbolAddress((void**)&pos, g_pos);
    cudaGetSymbolAddress((void**)&pooled, g_pooled);

    const float scale = 0.125f; // 1/sqrt(64)
    const long long tokRow = (long long)LL*DD;    // 512*768 per-batch stride in token tensors
    const long long scBatch = (long long)LL*LL;   // per (b,h) score tile
    const int NB = BB*HH;                         // 192 batched attention tiles

    // 1. Embedding + LN
    embed_kernel<<<NTOK, 256>>>(ids, we, pe, te, elnw, elnb, h);

    // 2. Mixup (layer 0): q/k from pre-blend h with layer-0 weights
    launch_gemm(h, Wq, bq, q, NTOK, DD, DD, DD, DD, DD, 1, 1, 0,0,0,0,0,0, nullptr, 1.f, 0, false);
    launch_gemm(h, Wk, bk, k, NTOK, DD, DD, DD, DD, DD, 1, 1, 0,0,0,0,0,0, nullptr, 1.f, 0, false);
    // cross scores: q[b] @ k[mix[b]]^T, batched over (b,h)
    launch_gemm(q, k, nullptr, sc, LL, LL, KDIM, DD, DD, LL,
                NB, HH,
                tokRow, KDIM,          // A: b-row stride, head stride
                tokRow, KDIM,          // B: (gathered b), head stride
                (long long)HH*scBatch, scBatch,
                mix, scale, 0, true);
    softmax_kernel<<<NB*LL, 128>>>(sc, amask, mix, HH*LL);
    crossmax_kernel<<<BB*LL, 128>>>(sc, cs);
    argmax_kernel<<<(BB*LL+255)/256, 256>>>(cs, pos);
    blend_kernel<<<(int)(((long long)NTOK*DD + 255)/256), 256>>>(h, pos, mix, alpha, x);
    cudaMemcpyAsync(h, x, (size_t)NTOK*DD*sizeof(float), cudaMemcpyDeviceToDevice);

    // 3. Transformer layers
    for (int i = 0; i < NLAYER; i++){
        const float* Wq_i = Wq + (long long)i*DD*DD;
        const float* bq_i = bq + i*DD;
        const float* Wk_i = Wk + (long long)i*DD*DD;
        const float* bk_i = bk + i*DD;
        const float* Wv_i = Wv + (long long)i*DD*DD;
        const float* bv_i = bv + i*DD;
        const float* Wo_i = Wo + (long long)i*DD*DD;
        const float* bo_i = bo + i*DD;
        const float* l1w  = ln1w + i*DD;
        const float* l1b  = ln1b + i*DD;
        const float* Wf1i = Wf1 + (long long)i*DD*FF;
        const float* bf1i = bf1 + i*FF;
        const float* Wf2i = Wf2 + (long long)i*FF*DD;
        const float* bf2i = bf2 + i*DD;
        const float* l2w  = ln2w + i*DD;
        const float* l2b  = ln2b + i*DD;

        launch_gemm(h, Wq_i, bq_i, q, NTOK, DD, DD, DD, DD, DD, 1,1, 0,0,0,0,0,0, nullptr, 1.f, 0, false);
        launch_gemm(h, Wk_i, bk_i, k, NTOK, DD, DD, DD, DD, DD, 1,1, 0,0,0,0,0,0, nullptr, 1.f, 0, false);
        launch_gemm(h, Wv_i, bv_i, v, NTOK, DD, DD, DD, DD, DD, 1,1, 0,0,0,0,0,0, nullptr, 1.f, 0, false);

        // scores = scale * q @ k^T  (batched over b,h)
        launch_gemm(q, k, nullptr, sc, LL, LL, KDIM, DD, DD, LL,
                    NB, HH, tokRow, KDIM, tokRow, KDIM,
                    (long long)HH*scBatch, scBatch, nullptr, scale, 0, true);
        softmax_kernel<<<NB*LL, 128>>>(sc, amask, nullptr, HH*LL);
        // attnout = scores @ v -> [b, l, h*64+vd]
        launch_gemm(sc, v, nullptr, ao, LL, KDIM, LL, LL, DD, DD,
                    NB, HH, (long long)HH*scBatch, scBatch,
                    tokRow, KDIM, tokRow, KDIM, nullptr, 1.f, 0, false);

        launch_gemm(ao, Wo_i, bo_i, x, NTOK, DD, DD, DD, DD, DD, 1,1, 0,0,0,0,0,0, nullptr, 1.f, 0, false);
        add_ln_kernel<<<NTOK, 256>>>(h, x, l1w, l1b);

        launch_gemm(h, Wf1i, bf1i, ff, NTOK, FF, DD, DD, FF, FF, 1,1, 0,0,0,0,0,0, nullptr, 1.f, 1, false);
        launch_gemm(ff, Wf2i, bf2i, x, NTOK, DD, FF, FF, DD, DD, 1,1, 0,0,0,0,0,0, nullptr, 1.f, 0, false);
        add_ln_kernel<<<NTOK, 256>>>(h, x, l2w, l2b);
    }

    // 4. Pool + classifier head
    pool_kernel<<<(BB*DD+255)/256, 256>>>(h, pooled);
    head_kernel<<<BB, 128>>>(pooled, c1w, c1b, c2w, c2b, (float*)d_out);
}

// round 3
// speedup vs baseline: 2.3958x; 2.3958x over previous
#include <cuda_runtime.h>
#include <mma.h>
#include <math.h>
#include <stdint.h>

using namespace nvcuda;

// Problem constants
#define BB 16
#define LL 512
#define DD 768
#define HH 12
#define KDIM 64
#define FF 3072
#define NLAYER 12
#define NTOK (BB*LL)            // 8192

// ---------------- device scratch ----------------
__device__ float g_h[NTOK*DD];
__device__ float g_x[NTOK*DD];
__device__ float g_q[NTOK*DD];
__device__ float g_k[NTOK*DD];
__device__ float g_v[NTOK*DD];
__device__ float g_ao[NTOK*DD];
__device__ float g_ff[NTOK*FF];
__device__ float g_scores[(long long)BB*HH*LL*LL];
__device__ float g_csim[BB*LL*LL];
__device__ int   g_pos[BB*LL];
__device__ float g_pooled[BB*DD];
__device__ float g_wqT[NLAYER*DD*DD];
__device__ float g_wkT[NLAYER*DD*DD];
__device__ float g_wvT[NLAYER*DD*DD];
__device__ float g_woT[NLAYER*DD*DD];
__device__ float g_wf1T[(long long)NLAYER*DD*FF];
__device__ float g_wf2T[(long long)NLAYER*DD*FF];
__device__ float g_vt[BB*HH*KDIM*LL];   // v transposed per (b,h): [64,512]

// ---------------- cp.async helpers ----------------
__device__ __forceinline__ void cp16(uint32_t dst, const void* src){
    asm volatile("cp.async.ca.shared.global [%0], [%1], 16;" :: "r"(dst), "l"(src));
}
__device__ __forceinline__ void cp_commit(){ asm volatile("cp.async.commit_group;"); }
__device__ __forceinline__ void cp_wait1(){ asm volatile("cp.async.wait_group 1;"); }
__device__ __forceinline__ void cp_wait0(){ asm volatile("cp.async.wait_group 0;"); }

// =============== wmma tf32 GEMM ===============
// C[M,N] = act(alpha * A[M,K] @ Bt[N,K]^T + bias)
// Block tile: BM=WMW*64 x BN=WNW*32. Warp tile 64x32 (4x2 m16n16k8 frags).
// K staged in chunks of 32, cp.async double-buffered, pitch-36 smem.
template<int WMW, int WNW>
__global__ void __launch_bounds__(WMW*WNW*32)
wmma_gemm(const float* __restrict__ A, const float* __restrict__ Bt,
          const float* __restrict__ bias, float* __restrict__ C,
          int K, int lda, int ldb, int ldc, int mapdiv,
          long long sAo, long long sAi, long long sBo, long long sBi,
          long long sCo, long long sCi, float alpha, int act)
{
    constexpr int BM = WMW*64, BN = WNW*32, PITCH = 36;
    constexpr int NTHR = WMW*WNW*32;
    extern __shared__ float sm[];
    const uint32_t sb = (uint32_t)__cvta_generic_to_shared(sm);

    int z = blockIdx.z;
    int zo = z / mapdiv, zi = z - zo*mapdiv;
    const float* Ab = A + (long long)zo*sAo + (long long)zi*sAi;
    const float* Bb = Bt + (long long)zo*sBo + (long long)zi*sBi;
    float* Cb = C + (long long)zo*sCo + (long long)zi*sCi;

    const int bm = blockIdx.y*BM, bn = blockIdx.x*BN;
    const int tid = threadIdx.x;
    const int warp = tid >> 5, lane = tid & 31;
    const int wm = warp / WNW, wn = warp % WNW;

    wmma::fragment<wmma::accumulator,16,16,8,float> acc[4][2];
    #pragma unroll
    for (int i=0;i<4;i++)
        #pragma unroll
        for (int j=0;j<2;j++) wmma::fill_fragment(acc[i][j], 0.0f);

    auto loadStage = [&](int s, int buf){
        const int k0 = s << 5;
        uint32_t aBase = sb + (uint32_t)(buf ? BM*PITCH*4 : 0);
        uint32_t bBase = sb + (uint32_t)((2*BM*PITCH + buf*BN*PITCH)*4);
        #pragma unroll
        for (int t = 0; t < (BM*8)/NTHR; t++){
            int idx = tid + t*NTHR;
            int row = idx >> 3, c4 = (idx & 7) * 4;
            cp16(aBase + (uint32_t)((row*PITCH + c4)*4),
                 Ab + (long long)(bm + row)*lda + k0 + c4);
        }
        #pragma unroll
        for (int t = 0; t < (BN*8)/NTHR; t++){
            int idx = tid + t*NTHR;
            int row = idx >> 3, c4 = (idx & 7) * 4;
            cp16(bBase + (uint32_t)((row*PITCH + c4)*4),
                 Bb + (long long)(bn + row)*ldb + k0 + c4);
        }
        cp_commit();
    };

    const int S = K >> 5;
    loadStage(0, 0);
    for (int s = 0; s < S; s++){
        if (s + 1 < S){ loadStage(s+1, (s+1)&1); cp_wait1(); }
        else          { cp_wait0(); }
        __syncthreads();
        const float* As = sm + (s&1 ? BM*PITCH : 0);
        const float* Bs = sm + 2*BM*PITCH + (s&1 ? BN*PITCH : 0);
        #pragma unroll
        for (int kk = 0; kk < 4; kk++){
            wmma::fragment<wmma::matrix_a,16,16,8,wmma::precision::tf32,wmma::row_major> af[4];
            #pragma unroll
            for (int i=0;i<4;i++){
                wmma::load_matrix_sync(af[i], As + (wm*64 + i*16)*PITCH + kk*8, PITCH);
                #pragma unroll
                for (int e=0;e<af[i].num_elements;e++) af[i].x[e] = wmma::__float_to_tf32(af[i].x[e]);
            }
            #pragma unroll
            for (int j=0;j<2;j++){
                wmma::fragment<wmma::matrix_b,16,16,8,wmma::precision::tf32,wmma::col_major> bf;
                wmma::load_matrix_sync(bf, Bs + (wn*32 + j*16)*PITCH + kk*8, PITCH);
                #pragma unroll
                for (int e=0;e<bf.num_elements;e++) bf.x[e] = wmma::__float_to_tf32(bf.x[e]);
                #pragma unroll
                for (int i=0;i<4;i++) wmma::mma_sync(acc[i][j], af[i], bf, acc[i][j]);
            }
        }
        __syncthreads();
    }

    // Epilogue: per-warp smem staging, then coalesced row writes with bias/act.
    float* wout = sm + warp*(64*PITCH);
    #pragma unroll
    for (int i=0;i<4;i++)
        #pragma unroll
        for (int j=0;j<2;j++){
            #pragma unroll
            for (int e=0;e<acc[i][j].num_elements;e++) acc[i][j].x[e] *= alpha;
            wmma::store_matrix_sync(wout + (i*16)*PITCH + j*16, acc[i][j], PITCH, wmma::mem_row_major);
        }
    __syncwarp();
    {
        const int colg = bn + wn*32 + lane;
        const float bb = bias ? bias[colg] : 0.f;
        const int rowg0 = bm + wm*64;
        #pragma unroll 4
        for (int r = 0; r < 64; r++){
            float v = wout[r*PITCH + lane] + bb;
            if (act == 1) v = 0.5f*v*(1.0f + erff(v*0.70710678118654752f));
            Cb[(long long)(rowg0 + r)*ldc + colg] = v;
        }
    }
}

// =============== transposes ===============
__global__ void wtrans_kernel(const float* __restrict__ src, float* __restrict__ dst, int K, int N)
{
    __shared__ float tile[32][33];
    int z = blockIdx.z;
    int n0 = blockIdx.x*32, k0 = blockIdx.y*32;
    const float* s = src + (long long)z*K*N;
    float* d = dst + (long long)z*N*K;
    for (int yy = threadIdx.y; yy < 32; yy += 8)
        tile[yy][threadIdx.x] = s[(long long)(k0+yy)*N + n0 + threadIdx.x];
    __syncthreads();
    for (int yy = threadIdx.y; yy < 32; yy += 8)
        d[(long long)(n0+yy)*K + k0 + threadIdx.x] = tile[threadIdx.x][yy];
}
__global__ void vtrans_kernel(const float* __restrict__ v, float* __restrict__ vt)
{
    __shared__ float tile[32][33];
    int z = blockIdx.z; int b = z/HH, h = z%HH;
    int l0 = blockIdx.x*32, d0 = blockIdx.y*32;
    for (int yy = threadIdx.y; yy < 32; yy += 8)
        tile[yy][threadIdx.x] = v[((long long)(b*LL + l0+yy))*DD + h*KDIM + d0 + threadIdx.x];
    __syncthreads();
    for (int yy = threadIdx.y; yy < 32; yy += 8)
        vt[((long long)z*KDIM + d0+yy)*LL + l0 + threadIdx.x] = tile[threadIdx.x][yy];
}

// ---------------- reductions ----------------
__device__ __forceinline__ float warpSum(float v){
    #pragma unroll
    for (int o=16;o>0;o>>=1) v += __shfl_xor_sync(0xffffffffu, v, o);
    return v;
}
__device__ __forceinline__ float warpMax(float v){
    #pragma unroll
    for (int o=16;o>0;o>>=1) v = fmaxf(v, __shfl_xor_sync(0xffffffffu, v, o));
    return v;
}
__device__ float blockSum(float v){
    __shared__ float sh[32];
    int lane = threadIdx.x & 31, wid = threadIdx.x >> 5;
    v = warpSum(v);
    if (lane==0) sh[wid] = v;
    __syncthreads();
    int nw = (blockDim.x + 31) >> 5;
    float r = (threadIdx.x < nw) ? sh[threadIdx.x] : 0.f;
    if (wid==0) r = warpSum(r);
    if (threadIdx.x==0) sh[0] = r;
    __syncthreads();
    r = sh[0];
    __syncthreads();
    return r;
}
__device__ float blockMax(float v){
    __shared__ float sh[32];
    int lane = threadIdx.x & 31, wid = threadIdx.x >> 5;
    v = warpMax(v);
    if (lane==0) sh[wid] = v;
    __syncthreads();
    int nw = (blockDim.x + 31) >> 5;
    float r = (threadIdx.x < nw) ? sh[threadIdx.x] : -INFINITY;
    if (wid==0) r = warpMax(r);
    if (threadIdx.x==0) sh[0] = r;
    __syncthreads();
    r = sh[0];
    __syncthreads();
    return r;
}

// ---------------- fp32 SGEMM (mixup path only) ----------------
template<bool TB>
__global__ __launch_bounds__(256)
void sgemm_kernel(const float* __restrict__ A, const float* __restrict__ B,
                  const float* __restrict__ bias, float* __restrict__ C,
                  int M, int N, int K, int lda, int ldb, int ldc,
                  int mapdiv,
                  long long sAo, long long sAi,
                  long long sBo, long long sBi,
                  long long sCo, long long sCi,
                  const int* __restrict__ bmap,
                  float alpha, int act)
{
    __shared__ float As[8][128];
    __shared__ float Bs[8][128];

    int z = blockIdx.z;
    int zo = z / mapdiv, zi = z - zo*mapdiv;
    const float* Ab = A + (long long)zo*sAo + (long long)zi*sAi;
    long long bzo = bmap ? (long long)bmap[zo] : (long long)zo;
    const float* Bb = B + bzo*sBo + (long long)zi*sBi;
    float* Cb = C + (long long)zo*sCo + (long long)zi*sCi;

    int bm = blockIdx.y * 128;
    int bn = blockIdx.x * 128;
    int tid = threadIdx.x;
    int tx = tid & 15, ty = tid >> 4;

    float acc[8][8];
    #pragma unroll
    for (int i=0;i<8;i++)
        #pragma unroll
        for (int j=0;j<8;j++) acc[i][j]=0.f;

    int arow = tid >> 1;
    int acol0 = (tid & 1) * 4;

    for (int k0 = 0; k0 < K; k0 += 8) {
        #pragma unroll
        for (int i=0;i<4;i++){
            int kk = acol0 + i;
            int gm = bm + arow;
            float val = 0.f;
            if (gm < M && (k0+kk) < K) val = Ab[(long long)gm*lda + (k0+kk)];
            As[kk][arow] = val;
        }
        if (!TB) {
            int brow = tid >> 5;
            int bcol0 = (tid & 31) * 4;
            #pragma unroll
            for (int i=0;i<4;i++){
                int nn = bcol0 + i;
                float val = 0.f;
                if ((k0+brow) < K && (bn+nn) < N) val = Bb[(long long)(k0+brow)*ldb + (bn+nn)];
                Bs[brow][nn] = val;
            }
        } else {
            int nrow = tid >> 1;
            int kcol0 = (tid & 1) * 4;
            #pragma unroll
            for (int i=0;i<4;i++){
                int kk = kcol0 + i;
                float val = 0.f;
                if ((bn+nrow) < N && (k0+kk) < K) val = Bb[(long long)(bn+nrow)*ldb + (k0+kk)];
                Bs[kk][nrow] = val;
            }
        }
        __syncthreads();
        #pragma unroll
        for (int kk=0; kk<8; kk++){
            float ar[8], br[8];
            #pragma unroll
            for (int i=0;i<8;i++) ar[i] = As[kk][ty*8+i];
            #pragma unroll
            for (int j=0;j<8;j++) br[j] = Bs[kk][tx*8+j];
            #pragma unroll
            for (int i=0;i<8;i++)
                #pragma unroll
                for (int j=0;j<8;j++)
                    acc[i][j] = fmaf(ar[i], br[j], acc[i][j]);
        }
        __syncthreads();
    }

    #pragma unroll
    for (int i=0;i<8;i++){
        int gm = bm + ty*8 + i;
        if (gm >= M) continue;
        #pragma unroll
        for (int j=0;j<8;j++){
            int gn = bn + tx*8 + j;
            if (gn >= N) continue;
            float val = acc[i][j]*alpha;
            if (bias) val += bias[gn];
            if (act==1) val = 0.5f*val*(1.0f + erff(val*0.70710678118654752f));
            Cb[(long long)gm*ldc + gn] = val;
        }
    }
}

// ---------------- embedding + LN ----------------
__global__ void embed_kernel(const int* __restrict__ ids,
                             const float* __restrict__ we,
                             const float* __restrict__ pe,
                             const float* __restrict__ te,
                             const float* __restrict__ w,
                             const float* __restrict__ b,
                             float* __restrict__ h)
{
    int t = blockIdx.x;
    int l = t % LL;
    int id = ids[t];
    float x[3];
    #pragma unroll
    for (int i=0;i<3;i++){
        int d = threadIdx.x + i*256;
        x[i] = we[(long long)id*DD + d] + pe[l*DD + d] + te[d];
    }
    float s = x[0]+x[1]+x[2];
    s = blockSum(s);
    float mu = s * (1.f/DD);
    float vs = 0.f;
    #pragma unroll
    for (int i=0;i<3;i++){ float dfr = x[i]-mu; vs += dfr*dfr; }
    vs = blockSum(vs);
    float inv = rsqrtf(vs*(1.f/DD) + 1e-12f);
    #pragma unroll
    for (int i=0;i<3;i++){
        int d = threadIdx.x + i*256;
        h[(long long)t*DD + d] = (x[i]-mu)*inv*w[d] + b[d];
    }
}

__global__ void add_ln_kernel(float* __restrict__ h, const float* __restrict__ r,
                              const float* __restrict__ w, const float* __restrict__ b)
{
    int t = blockIdx.x;
    float x[3];
    #pragma unroll
    for (int i=0;i<3;i++){
        int d = threadIdx.x + i*256;
        long long idx = (long long)t*DD + d;
        x[i] = h[idx] + r[idx];
    }
    float s = x[0]+x[1]+x[2];
    s = blockSum(s);
    float mu = s * (1.f/DD);
    float vs = 0.f;
    #pragma unroll
    for (int i=0;i<3;i++){ float dfr = x[i]-mu; vs += dfr*dfr; }
    vs = blockSum(vs);
    float inv = rsqrtf(vs*(1.f/DD) + 1e-12f);
    #pragma unroll
    for (int i=0;i<3;i++){
        int d = threadIdx.x + i*256;
        h[(long long)t*DD + d] = (x[i]-mu)*inv*w[d] + b[d];
    }
}

// ---------------- masked softmax (rows of 512) ----------------
__global__ void softmax_kernel(float* __restrict__ sc, const float* __restrict__ amask,
                               const int* __restrict__ mix, int HL)
{
    int r = blockIdx.x;
    int b = r / HL;
    float* row = sc + (long long)r * LL;
    int mb = mix ? mix[b] : b;
    const float* m = amask + (long long)mb * LL;

    float vals[4], ms[4];
    float mx = -INFINITY;
    #pragma unroll
    for (int i=0;i<4;i++){
        int j = threadIdx.x + i*128;
        ms[i] = m[j];
        vals[i] = row[j]*ms[i];
        mx = fmaxf(mx, vals[i]);
    }
    mx = blockMax(mx);
    float s = 0.f;
    #pragma unroll
    for (int i=0;i<4;i++){
        vals[i] = expf(vals[i]-mx)*ms[i];
        s += vals[i];
    }
    s = blockSum(s);
    if (s == 0.f) s = 1.f;
    float inv = 1.f/s;
    #pragma unroll
    for (int i=0;i<4;i++){
        int j = threadIdx.x + i*128;
        row[j] = vals[i]*inv;
    }
}

__global__ void crossmax_kernel(const float* __restrict__ sc, float* __restrict__ cs)
{
    int r = blockIdx.x;
    int b = r / LL;
    int l = r % LL;
    #pragma unroll
    for (int i=0;i<4;i++){
        int j = threadIdx.x + i*128;
        float mx = -INFINITY;
        #pragma unroll
        for (int hh=0; hh<HH; hh++){
            mx = fmaxf(mx, sc[(((long long)(b*HH+hh))*LL + l)*LL + j]);
        }
        cs[(long long)r*LL + j] = mx;
    }
}

__global__ void argmax_kernel(const float* __restrict__ cs, int* __restrict__ pos)
{
    int idx = blockIdx.x*blockDim.x + threadIdx.x;
    if (idx >= BB*LL) return;
    int l = idx % LL;
    int lo, hi;
    if (l == 0)        { lo = 0;     hi = 0;     }
    else if (l == LL-1){ lo = LL-1;  hi = LL-1;  }
    else               { lo = 1;     hi = LL-2;  }
    const float* row = cs + (long long)idx*LL;
    float best = -INFINITY; int bi = lo;
    for (int j=lo; j<=hi; j++){
        float v = row[j];
        if (v >= best){ best = v; bi = j; }
    }
    pos[idx] = bi;
}

__global__ void blend_kernel(const float* __restrict__ h, const int* __restrict__ pos,
                             const int* __restrict__ mix, const float* __restrict__ alpha_p,
                             float* __restrict__ out)
{
    long long i = (long long)blockIdx.x*blockDim.x + threadIdx.x;
    if (i >= (long long)NTOK*DD) return;
    int d = (int)(i % DD);
    long long t = i / DD;
    int b = (int)(t / LL);
    float a = *alpha_p;
    int p = pos[t];
    float h2 = h[((long long)(mix[b]*LL + p))*DD + d];
    out[i] = a*h[i] + (1.f-a)*h2;
}

__global__ void pool_kernel(const float* __restrict__ h, float* __restrict__ pooled)
{
    int i = blockIdx.x*blockDim.x + threadIdx.x;
    if (i >= BB*DD) return;
    int b = i / DD, d = i % DD;
    float s = 0.f;
    for (int l=0; l<LL; l++) s += h[((long long)b*LL + l)*DD + d];
    pooled[i] = s * (1.f/LL);
}

__global__ void head_kernel(const float* __restrict__ pooled,
                            const float* __restrict__ c1w, const float* __restrict__ c1b,
                            const float* __restrict__ c2w, const float* __restrict__ c2b,
                            float* __restrict__ out)
{
    __shared__ float hid[128];
    int b = blockIdx.x;
    int j = threadIdx.x;
    float s = c1b[j];
    for (int d=0; d<DD; d++) s += pooled[b*DD + d] * c1w[d*128 + j];
    hid[j] = tanhf(s);
    __syncthreads();
    if (j < 4){
        float o = c2b[j];
        for (int kk=0; kk<128; kk++) o += hid[kk]*c2w[kk*4 + j];
        out[b*4 + j] = o;
    }
}

// ---------------- host wrappers ----------------
static void launch_sgemm(const float* A, const float* B, const float* bias, float* C,
                        int M, int N, int K, int lda, int ldb, int ldc,
                        int batches, int mapdiv,
                        long long sAo, long long sAi,
                        long long sBo, long long sBi,
                        long long sCo, long long sCi,
                        const int* bmap, float alpha, int act, bool transB)
{
    dim3 grid((N+127)/128, (M+127)/128, batches);
    if (transB)
        sgemm_kernel<true><<<grid, 256>>>(A,B,bias,C,M,N,K,lda,ldb,ldc,mapdiv,
                                          sAo,sAi,sBo,sBi,sCo,sCi,bmap,alpha,act);
    else
        sgemm_kernel<false><<<grid, 256>>>(A,B,bias,C,M,N,K,lda,ldb,ldc,mapdiv,
                                           sAo,sAi,sBo,sBi,sCo,sCi,bmap,alpha,act);
}

// wmma gemm launcher; nt = 128 or 64 (BN)
static void launch_tc(int nt, const float* A, const float* Bt, const float* bias, float* C,
                      int M, int N, int K, int lda, int ldb, int ldc,
                      int batches, int mapdiv,
                      long long sAo, long long sAi, long long sBo, long long sBi,
                      long long sCo, long long sCi, float alpha, int act)
{
    if (nt == 128){
        constexpr int SMEMB = (2*(128+128)*36)*4;   // 73728
        cudaFuncSetAttribute(wmma_gemm<2,4>, cudaFuncAttributeMaxDynamicSharedMemorySize, SMEMB);
        dim3 grid(N/128, M/128, batches);
        wmma_gemm<2,4><<<grid, 256, SMEMB>>>(A,Bt,bias,C,K,lda,ldb,ldc,mapdiv,
                                             sAo,sAi,sBo,sBi,sCo,sCi,alpha,act);
    } else {
        constexpr int SMEMB = (2*(128+64)*36)*4;    // 55296
        cudaFuncSetAttribute(wmma_gemm<2,2>, cudaFuncAttributeMaxDynamicSharedMemorySize, SMEMB);
        dim3 grid(N/64, M/128, batches);
        wmma_gemm<2,2><<<grid, 128, SMEMB>>>(A,Bt,bias,C,K,lda,ldb,ldc,mapdiv,
                                             sAo,sAi,sBo,sBi,sCo,sCi,alpha,act);
    }
}

extern "C" void kernel_launch(void* const* d_in, const int* in_sizes, int n_in,
                              void* d_out, int out_size)
{
    const int*   ids    = (const int*)  d_in[0];
    const float* amask  = (const float*)d_in[1];
    const int*   mix    = (const int*)  d_in[2];
    const float* alpha  = (const float*)d_in[6];
    const float* we     = (const float*)d_in[7];
    const float* pe     = (const float*)d_in[8];
    const float* te     = (const float*)d_in[9];
    const float* elnw   = (const float*)d_in[10];
    const float* elnb   = (const float*)d_in[11];
    const float* Wq     = (const float*)d_in[12];
    const float* bq     = (const float*)d_in[13];
    const float* Wk     = (const float*)d_in[14];
    const float* bk     = (const float*)d_in[15];
    const float* Wv     = (const float*)d_in[16];
    const float* bv     = (const float*)d_in[17];
    const float* Wo     = (const float*)d_in[18];
    const float* bo     = (const float*)d_in[19];
    const float* ln1w   = (const float*)d_in[20];
    const float* ln1b   = (const float*)d_in[21];
    const float* Wf1    = (const float*)d_in[22];
    const float* bf1    = (const float*)d_in[23];
    const float* Wf2    = (const float*)d_in[24];
    const float* bf2    = (const float*)d_in[25];
    const float* ln2w   = (const float*)d_in[26];
    const float* ln2b   = (const float*)d_in[27];
    const float* c1w    = (const float*)d_in[28];
    const float* c1b    = (const float*)d_in[29];
    const float* c2w    = (const float*)d_in[30];
    const float* c2b    = (const float*)d_in[31];

    float *h, *x, *q, *k, *v, *ao, *ff, *sc, *cs, *pooled, *vt;
    float *wqT, *wkT, *wvT, *woT, *wf1T, *wf2T;
    int *pos;
    cudaGetSymbolAddress((void**)&h,  g_h);
    cudaGetSymbolAddress((void**)&x,  g_x);
    cudaGetSymbolAddress((void**)&q,  g_q);
    cudaGetSymbolAddress((void**)&k,  g_k);
    cudaGetSymbolAddress((void**)&v,  g_v);
    cudaGetSymbolAddress((void**)&ao, g_ao);
    cudaGetSymbolAddress((void**)&ff, g_ff);
    cudaGetSymbolAddress((void**)&sc, g_scores);
    cudaGetSymbolAddress((void**)&cs, g_csim);
    cudaGetSymbolAddress((void**)&pos, g_pos);
    cudaGetSymbolAddress((void**)&pooled, g_pooled);
    cudaGetSymbolAddress((void**)&vt, g_vt);
    cudaGetSymbolAddress((void**)&wqT, g_wqT);
    cudaGetSymbolAddress((void**)&wkT, g_wkT);
    cudaGetSymbolAddress((void**)&wvT, g_wvT);
    cudaGetSymbolAddress((void**)&woT, g_woT);
    cudaGetSymbolAddress((void**)&wf1T, g_wf1T);
    cudaGetSymbolAddress((void**)&wf2T, g_wf2T);

    const float scale = 0.125f;
    const long long tokRow = (long long)LL*DD;
    const long long scB = (long long)LL*LL;
    const int NB = BB*HH;

    // 0. Pre-transpose all weights to [N,K]
    {
        dim3 blk(32,8);
        wtrans_kernel<<<dim3(DD/32, DD/32, NLAYER), blk>>>(Wq, wqT, DD, DD);
        wtrans_kernel<<<dim3(DD/32, DD/32, NLAYER), blk>>>(Wk, wkT, DD, DD);
        wtrans_kernel<<<dim3(DD/32, DD/32, NLAYER), blk>>>(Wv, wvT, DD, DD);
        wtrans_kernel<<<dim3(DD/32, DD/32, NLAYER), blk>>>(Wo, woT, DD, DD);
        wtrans_kernel<<<dim3(FF/32, DD/32, NLAYER), blk>>>(Wf1, wf1T, DD, FF);
        wtrans_kernel<<<dim3(DD/32, FF/32, NLAYER), blk>>>(Wf2, wf2T, FF, DD);
    }

    // 1. Embedding + LN
    embed_kernel<<<NTOK, 256>>>(ids, we, pe, te, elnw, elnb, h);

    // 2. Mixup (layer 0) — fp32 for argmax robustness
    launch_sgemm(h, Wq, bq, q, NTOK, DD, DD, DD, DD, DD, 1, 1, 0,0,0,0,0,0, nullptr, 1.f, 0, false);
    launch_sgemm(h, Wk, bk, k, NTOK, DD, DD, DD, DD, DD, 1, 1, 0,0,0,0,0,0, nullptr, 1.f, 0, false);
    launch_sgemm(q, k, nullptr, sc, LL, LL, KDIM, DD, DD, LL,
                 NB, HH, tokRow, KDIM, tokRow, KDIM,
                 (long long)HH*scB, scB, mix, scale, 0, true);
    softmax_kernel<<<NB*LL, 128>>>(sc, amask, mix, HH*LL);
    crossmax_kernel<<<BB*LL, 128>>>(sc, cs);
    argmax_kernel<<<(BB*LL+255)/256, 256>>>(cs, pos);
    blend_kernel<<<(int)(((long long)NTOK*DD + 255)/256), 256>>>(h, pos, mix, alpha, x);
    cudaMemcpyAsync(h, x, (size_t)NTOK*DD*sizeof(float), cudaMemcpyDeviceToDevice);

    // 3. Transformer layers (wmma tf32 GEMMs)
    for (int i = 0; i < NLAYER; i++){
        const float* wqT_i = wqT + (long long)i*DD*DD;
        const float* wkT_i = wkT + (long long)i*DD*DD;
        const float* wvT_i = wvT + (long long)i*DD*DD;
        const float* woT_i = woT + (long long)i*DD*DD;
        const float* wf1T_i = wf1T + (long long)i*DD*FF;
        const float* wf2T_i = wf2T + (long long)i*DD*FF;
        const float* bq_i = bq + i*DD;
        const float* bk_i = bk + i*DD;
        const float* bv_i = bv + i*DD;
        const float* bo_i = bo + i*DD;
        const float* bf1i = bf1 + i*FF;
        const float* bf2i = bf2 + i*DD;
        const float* l1w  = ln1w + i*DD;
        const float* l1b  = ln1b + i*DD;
        const float* l2w  = ln2w + i*DD;
        const float* l2b  = ln2b + i*DD;

        launch_tc(128, h, wqT_i, bq_i, q, NTOK, DD, DD, DD, DD, DD, 1,1, 0,0,0,0,0,0, 1.f, 0);
        launch_tc(128, h, wkT_i, bk_i, k, NTOK, DD, DD, DD, DD, DD, 1,1, 0,0,0,0,0,0, 1.f, 0);
        launch_tc(128, h, wvT_i, bv_i, v, NTOK, DD, DD, DD, DD, DD, 1,1, 0,0,0,0,0,0, 1.f, 0);

        // scores = scale * q @ k^T  (A=q rows, B=k rows, both K-major with ld=768)
        launch_tc(128, q, k, nullptr, sc, LL, LL, KDIM, DD, DD, LL,
                  NB, HH, tokRow, KDIM, tokRow, KDIM,
                  (long long)HH*scB, scB, scale, 0);
        softmax_kernel<<<NB*LL, 128>>>(sc, amask, nullptr, HH*LL);

        // v transpose per (b,h): vt[(b,h)][64][512]
        vtrans_kernel<<<dim3(LL/32, KDIM/32, NB), dim3(32,8)>>>(v, vt);
        // attnout = scores @ v  (B = vt [64,512] K-major)
        launch_tc(64, sc, vt, nullptr, ao, LL, KDIM, LL, LL, LL, DD,
                  NB, HH, (long long)HH*scB, scB,
                  (long long)HH*KDIM*LL, (long long)KDIM*LL,
                  tokRow, KDIM, 1.f, 0);

        launch_tc(128, ao, woT_i, bo_i, x, NTOK, DD, DD, DD, DD, DD, 1,1, 0,0,0,0,0,0, 1.f, 0);
        add_ln_kernel<<<NTOK, 256>>>(h, x, l1w, l1b);

        launch_tc(128, h, wf1T_i, bf1i, ff, NTOK, FF, DD, DD, DD, FF, 1,1, 0,0,0,0,0,0, 1.f, 1);
        launch_tc(128, ff, wf2T_i, bf2i, x, NTOK, DD, FF, FF, FF, DD, 1,1, 0,0,0,0,0,0, 1.f, 0);
        add_ln_kernel<<<NTOK, 256>>>(h, x, l2w, l2b);
    }

    // 4. Pool + classifier head
    pool_kernel<<<(BB*DD+255)/256, 256>>>(h, pooled);
    head_kernel<<<BB, 128>>>(pooled, c1w, c1b, c2w, c2b, (float*)d_out);
}